// round 16
// baseline (speedup 1.0000x reference)
#include <cuda_runtime.h>
#include <cuda_bf16.h>
#include <cstdint>

// VQ cdist: out[n,k] = sqrt(max(||x_n||^2 + ||e_k||^2 - 2 x_n.e_k, 0))
// N=65536, K=1024, D=64.  mma.sync path (tcgen05 rejected by compute_103).
//
// R16 = R15 + epilogue address strength-reduction: one stepped row pointer
// per thread (advanced by ng*BM*Kdim per iteration) + constant row deltas
// replaces per-tile 64-bit IMAD chains. All else identical to R15:
// Ebf = bf16(-2e) prep, acc init = xs+es (MMA yields dist^2), persistent B
// fragments, 4-stage distance-3 cp.async pipeline, 1 barrier/iter,
// sqrt.approx + __stcs, 2 CTAs/SM.

#define BM 128
#define BN 64

// smem layout: 4 A-stages (A 16KB + xs 512B each), then B 8KB, then es 256B
#define ST_XS  16384
#define STAGE  16896
#define B_OFF  (4 * STAGE)          // 67584
#define ES_OFF (B_OFF + 8192)       // 75776
#define DYN_SMEM (ES_OFF + 256)     // 76032  (x2 CTAs = 152KB <= 228KB)

#define MAXN 65536
#define MAXK 1024

__device__ __nv_bfloat16 g_Xbf[MAXN * 64];
__device__ float         g_xsq[MAXN];
__device__ __nv_bfloat16 g_Ebf[MAXK * 64];   // holds bf16(-2*e)
__device__ float         g_esq[MAXK];        // ||e||^2 of ORIGINAL e

#define SWZ(o) ((o) ^ (((o) >> 3) & 0x70))

__device__ __forceinline__ void ldsm_x4(uint32_t& r0, uint32_t& r1, uint32_t& r2, uint32_t& r3, uint32_t addr) {
    asm volatile("ldmatrix.sync.aligned.m8n8.x4.shared.b16 {%0,%1,%2,%3}, [%4];"
                 : "=r"(r0), "=r"(r1), "=r"(r2), "=r"(r3) : "r"(addr));
}

__device__ __forceinline__ void mma_bf16(float* c, const uint32_t* a, uint32_t b0, uint32_t b1) {
    asm volatile("mma.sync.aligned.m16n8k16.row.col.f32.bf16.bf16.f32 "
                 "{%0,%1,%2,%3}, {%4,%5,%6,%7}, {%8,%9}, {%0,%1,%2,%3};"
                 : "+f"(c[0]), "+f"(c[1]), "+f"(c[2]), "+f"(c[3])
                 : "r"(a[0]), "r"(a[1]), "r"(a[2]), "r"(a[3]), "r"(b0), "r"(b1));
}

__device__ __forceinline__ void cp16(uint32_t dst, const void* src) {
    asm volatile("cp.async.cg.shared.global [%0], [%1], 16;" :: "r"(dst), "l"(src) : "memory");
}

__device__ __forceinline__ void cp16_l2(uint32_t dst, const void* src) {
    asm volatile("cp.async.cg.shared.global.L2::256B [%0], [%1], 16;" :: "r"(dst), "l"(src) : "memory");
}

__device__ __forceinline__ float sqrt_approx(float x) {
    float r;
    asm("sqrt.approx.f32 %0, %1;" : "=f"(r) : "f"(x));
    return r;
}

// logical col l (within 16-group) -> physical smem row, so that mma fragment
// ownership {2t, 2t+1, 2t+8, 2t+9} (phys) maps to logical {4t..4t+3}.
__device__ __forceinline__ int bperm(int l) {
    int t = l >> 2, j = l & 3;
    return 2 * t + (j & 1) + ((j >> 1) << 3);
}

// ---------------- merged prep: fp32 -> bf16 (+E scaled by -2) + fp32 norms ----------------
__global__ __launch_bounds__(256)
void conv_all(const float* __restrict__ X, const float* __restrict__ E, int kblocks) {
    const int b    = blockIdx.x;
    const int tid  = threadIdx.x;
    const int lane = tid & 31;
    const float4* sv;
    __nv_bfloat16* drow;
    float* sqrow;
    float scale;
    if (b < kblocks) {
        sv    = reinterpret_cast<const float4*>(E) + (size_t)b * 2048;
        drow  = g_Ebf + (size_t)b * 8192;
        sqrow = g_esq + (size_t)b * 128;
        scale = -2.0f;
    } else {
        const int c = b - kblocks;
        sv    = reinterpret_cast<const float4*>(X) + (size_t)c * 2048;
        drow  = g_Xbf + (size_t)c * 8192;
        sqrow = g_xsq + (size_t)c * 128;
        scale = 1.0f;
    }
    #pragma unroll
    for (int i = 0; i < 8; i++) {
        const int f   = tid + i * 256;
        const int row = f >> 4;
        const int c4  = f & 15;
        float4 v = sv[f];
        float ss = v.x * v.x + v.y * v.y + v.z * v.z + v.w * v.w;  // norm of ORIGINAL
        __nv_bfloat162 p0 = __floats2bfloat162_rn(v.x * scale, v.y * scale);
        __nv_bfloat162 p1 = __floats2bfloat162_rn(v.z * scale, v.w * scale);
        uint2 pk;
        pk.x = *reinterpret_cast<uint32_t*>(&p0);
        pk.y = *reinterpret_cast<uint32_t*>(&p1);
        *reinterpret_cast<uint2*>(drow + row * 64 + c4 * 4) = pk;
        ss += __shfl_xor_sync(0xffffffffu, ss, 1);
        ss += __shfl_xor_sync(0xffffffffu, ss, 2);
        ss += __shfl_xor_sync(0xffffffffu, ss, 4);
        ss += __shfl_xor_sync(0xffffffffu, ss, 8);
        if ((lane & 15) == 0) sqrow[row] = ss;
    }
}

// ---------------- main ----------------
__device__ __forceinline__ void issue_A(uint32_t stg, int m0, int tid) {
    #pragma unroll
    for (int i = 0; i < 4; i++) {                  // 1024 chunks of 16B
        const int f   = tid + i * 256;
        const int row = f >> 3;
        const int c   = f & 7;
        cp16_l2(stg + SWZ((uint32_t)(row * 128 + c * 16)),
                g_Xbf + (size_t)(m0 + row) * 64 + c * 8);
    }
    if (tid < 32) cp16(stg + ST_XS + tid * 16, g_xsq + m0 + tid * 4);
}

__global__ __launch_bounds__(256, 2)
void vq_cdist_kernel(float* __restrict__ out, int Kdim, int nm, int nx) {
    extern __shared__ char smem[];
    const uint32_t s_base = (uint32_t)__cvta_generic_to_shared(smem);

    const int tid  = threadIdx.x;
    const int lane = tid & 31;
    const int wid  = tid >> 5;
    const int wm = (wid & 3) * 32;
    const int wn = (wid >> 2) * 32;

    const int group = blockIdx.x / nx;          // m-stripe group
    const int n0    = (blockIdx.x % nx) * BN;   // fixed n-tile for this CTA
    const int ng    = gridDim.x / nx;

    // ---- prologue: B tile + es (once), then first three A stages ----
    {
        const uint32_t b0 = s_base + B_OFF;
        #pragma unroll
        for (int i = 0; i < 2; i++) {              // 512 chunks (64 rows x 128B)
            const int f    = tid + i * 256;
            const int lrow = f >> 3;
            const int c    = f & 7;
            const int prow = (lrow & ~15) | bperm(lrow & 15);
            cp16(b0 + SWZ((uint32_t)(prow * 128 + c * 16)),
                 g_Ebf + (size_t)(n0 + lrow) * 64 + c * 8);
        }
        if (tid < 16) cp16(s_base + ES_OFF + tid * 16, g_esq + n0 + tid * 4);
        asm volatile("cp.async.commit_group;" ::: "memory");
    }
    // nm=512, ng>=16 -> every group has >= 26 tiles; prologue depth 3 is safe
    issue_A(s_base, group * BM, tid);
    asm volatile("cp.async.commit_group;" ::: "memory");
    issue_A(s_base + STAGE, (group + ng) * BM, tid);
    asm volatile("cp.async.commit_group;" ::: "memory");
    issue_A(s_base + 2 * STAGE, (group + 2 * ng) * BM, tid);
    asm volatile("cp.async.commit_group;" ::: "memory");

    asm volatile("cp.async.wait_group 3;" ::: "memory");       // B + es complete
    __syncthreads();

    // ---- persistent B fragments (32 regs) ----
    uint32_t bfr[4][2][4];
    #pragma unroll
    for (int ks = 0; ks < 4; ks++) {
        #pragma unroll
        for (int np = 0; np < 2; np++) {
            const int nr = wn + np * 16 + ((lane >> 4) & 1) * 8 + (lane & 7);
            const int kb = (ks * 16 + ((lane >> 3) & 1) * 8) * 2;
            ldsm_x4(bfr[ks][np][0], bfr[ks][np][1], bfr[ks][np][2], bfr[ks][np][3],
                    s_base + B_OFF + SWZ((uint32_t)(nr * 128 + kb)));
        }
    }
    // per-thread es values (8 floats), cached in registers
    const int rb = wm + (lane >> 2);
    const int t4 = (lane & 3) * 4;
    const float* es_s = reinterpret_cast<const float*>(smem + ES_OFF);
    const float4 esA = *reinterpret_cast<const float4*>(&es_s[wn + t4]);
    const float4 esB = *reinterpret_cast<const float4*>(&es_s[wn + 16 + t4]);

    // ---- stepped output pointer: row (m0+rb), col n0+wn; advance per iter ----
    float* orow = out + (size_t)(group * BM + rb) * Kdim + n0 + wn;
    const size_t ostep = (size_t)ng * BM * Kdim;   // elements per m-stride
    const int d8  = 8 * Kdim;                       // +8 rows (elements)
    const int d16 = 16 * Kdim;                      // +16 rows (elements)

    // ---- main loop: 4 stages, distance-3 prefetch, 1 barrier/iter ----
    int st = 0;
    for (int mi = group; mi < nm; mi += ng) {
        __syncthreads();   // tile mi published; stage st-1 (=(st+3)&3) now dead

        const int mi3 = mi + 3 * ng;
        if (mi3 < nm) {
            issue_A(s_base + ((st + 3) & 3) * STAGE, mi3 * BM, tid);
            asm volatile("cp.async.commit_group;" ::: "memory");
            asm volatile("cp.async.wait_group 3;" ::: "memory");
        } else if (mi + 2 * ng < nm) {
            asm volatile("cp.async.wait_group 2;" ::: "memory");
        } else if (mi + ng < nm) {
            asm volatile("cp.async.wait_group 1;" ::: "memory");
        } else {
            asm volatile("cp.async.wait_group 0;" ::: "memory");
        }

        const uint32_t a_base = s_base + st * STAGE;
        const float* xs_s = reinterpret_cast<const float*>(smem + st * STAGE + ST_XS);

        // ---- acc init = xs + es (MMA adds -2*cross onto it) ----
        float acc[2][4][4];
        #pragma unroll
        for (int mt = 0; mt < 2; mt++) {
            const float xsa = xs_s[rb + mt * 16];
            const float xsb = xs_s[rb + mt * 16 + 8];
            acc[mt][0][0] = xsa + esA.x;  acc[mt][0][1] = xsa + esA.y;
            acc[mt][1][0] = xsa + esA.z;  acc[mt][1][1] = xsa + esA.w;
            acc[mt][0][2] = xsb + esA.x;  acc[mt][0][3] = xsb + esA.y;
            acc[mt][1][2] = xsb + esA.z;  acc[mt][1][3] = xsb + esA.w;
            acc[mt][2][0] = xsa + esB.x;  acc[mt][2][1] = xsa + esB.y;
            acc[mt][3][0] = xsa + esB.z;  acc[mt][3][1] = xsa + esB.w;
            acc[mt][2][2] = xsb + esB.x;  acc[mt][2][3] = xsb + esB.y;
            acc[mt][3][2] = xsb + esB.z;  acc[mt][3][3] = xsb + esB.w;
        }

        #pragma unroll
        for (int ks = 0; ks < 4; ks++) {
            const int kc = ks * 16;
            uint32_t a_frag[2][4];
            #pragma unroll
            for (int mt = 0; mt < 2; mt++) {
                const int r  = wm + mt * 16 + (lane & 15);
                const int cb = (kc + ((lane >> 4) << 3)) * 2;
                ldsm_x4(a_frag[mt][0], a_frag[mt][1], a_frag[mt][2], a_frag[mt][3],
                        a_base + SWZ((uint32_t)(r * 128 + cb)));
            }
            #pragma unroll
            for (int np = 0; np < 2; np++) {
                #pragma unroll
                for (int mt = 0; mt < 2; mt++) {
                    mma_bf16(acc[mt][np * 2],     a_frag[mt], bfr[ks][np][0], bfr[ks][np][1]);
                    mma_bf16(acc[mt][np * 2 + 1], a_frag[mt], bfr[ks][np][2], bfr[ks][np][3]);
                }
            }
        }

        // ---- epilogue: acc IS dist^2; sqrt + store via stepped pointers ----
        #pragma unroll
        for (int mt = 0; mt < 2; mt++) {
            float* o0 = orow + (mt ? d16 : 0);
            float* o1 = o0 + d8;
            #pragma unroll
            for (int q = 0; q < 2; q++) {
                const int c = q * 16;
                float4 v0, v1;
                v0.x = sqrt_approx(acc[mt][2*q][0]);
                v0.y = sqrt_approx(acc[mt][2*q][1]);
                v0.z = sqrt_approx(acc[mt][2*q+1][0]);
                v0.w = sqrt_approx(acc[mt][2*q+1][1]);
                v1.x = sqrt_approx(acc[mt][2*q][2]);
                v1.y = sqrt_approx(acc[mt][2*q][3]);
                v1.z = sqrt_approx(acc[mt][2*q+1][2]);
                v1.w = sqrt_approx(acc[mt][2*q+1][3]);
                __stcs(reinterpret_cast<float4*>(o0 + c + t4), v0);
                __stcs(reinterpret_cast<float4*>(o1 + c + t4), v1);
            }
        }
        orow += ostep;

        st = (st + 1) & 3;
    }
}

extern "C" void kernel_launch(void* const* d_in, const int* in_sizes, int n_in,
                              void* d_out, int out_size) {
    const float* X = (const float*)d_in[0];   // inputs [N, 64]
    const float* E = (const float*)d_in[1];   // embeddings [K, 64]
    float* out = (float*)d_out;               // [N, K] fp32

    const int N = in_sizes[0] / 64;
    const int K = in_sizes[1] / 64;
    const int nx = K / BN;                    // 16
    const int nm = N / BM;                    // 512

    static int configured = 0;
    if (!configured) {
        cudaFuncSetAttribute(vq_cdist_kernel,
                             cudaFuncAttributeMaxDynamicSharedMemorySize, DYN_SMEM);
        configured = 1;
    }

    int sms = 148;
    cudaDeviceGetAttribute(&sms, cudaDevAttrMultiProcessorCount, 0);
    int grid = (2 * sms / nx) * nx;           // multiple of nx
    if (grid < nx) grid = nx;

    conv_all<<<K / 128 + N / 128, 256>>>(X, E, K / 128);
    vq_cdist_kernel<<<grid, 256, DYN_SMEM>>>(out, K, nm, nx);
}

// round 17
// speedup vs baseline: 1.0287x; 1.0287x over previous
#include <cuda_runtime.h>
#include <cuda_bf16.h>
#include <cstdint>

// VQ cdist: out[n,k] = sqrt(max(||x_n||^2 + ||e_k||^2 - 2 x_n.e_k, 0))
// N=65536, K=1024, D=64.  mma.sync path (tcgen05 rejected by compute_103).
//
// FINAL (= R15, best measured 47.8us; R16's address strength-reduction was
// within noise at the pipe level but regressed total — reverted).
// Design summary:
//  - prep kernel: X,E fp32 -> bf16 __device__ globals ONCE; E pre-scaled by
//    -2 (exact); exact fp32 row norms via shfl.
//  - main: persistent CTA pinned to one 64-col n-tile; B fragments built once
//    into registers; 4-stage cp.async A pipeline, prefetch distance 3,
//    ONE __syncthreads per iteration; acc initialized to xs+es so the MMA
//    (A x (-2E)) produces dist^2 directly; sqrt.approx + __stcs epilogue
//    with float4 stores via the permuted-B column placement. 2 CTAs/SM.

#define BM 128
#define BN 64

// smem layout: 4 A-stages (A 16KB + xs 512B each), then B 8KB, then es 256B
#define ST_XS  16384
#define STAGE  16896
#define B_OFF  (4 * STAGE)          // 67584
#define ES_OFF (B_OFF + 8192)       // 75776
#define DYN_SMEM (ES_OFF + 256)     // 76032  (x2 CTAs = 152KB <= 228KB)

#define MAXN 65536
#define MAXK 1024

__device__ __nv_bfloat16 g_Xbf[MAXN * 64];
__device__ float         g_xsq[MAXN];
__device__ __nv_bfloat16 g_Ebf[MAXK * 64];   // holds bf16(-2*e)
__device__ float         g_esq[MAXK];        // ||e||^2 of ORIGINAL e

#define SWZ(o) ((o) ^ (((o) >> 3) & 0x70))

__device__ __forceinline__ void ldsm_x4(uint32_t& r0, uint32_t& r1, uint32_t& r2, uint32_t& r3, uint32_t addr) {
    asm volatile("ldmatrix.sync.aligned.m8n8.x4.shared.b16 {%0,%1,%2,%3}, [%4];"
                 : "=r"(r0), "=r"(r1), "=r"(r2), "=r"(r3) : "r"(addr));
}

__device__ __forceinline__ void mma_bf16(float* c, const uint32_t* a, uint32_t b0, uint32_t b1) {
    asm volatile("mma.sync.aligned.m16n8k16.row.col.f32.bf16.bf16.f32 "
                 "{%0,%1,%2,%3}, {%4,%5,%6,%7}, {%8,%9}, {%0,%1,%2,%3};"
                 : "+f"(c[0]), "+f"(c[1]), "+f"(c[2]), "+f"(c[3])
                 : "r"(a[0]), "r"(a[1]), "r"(a[2]), "r"(a[3]), "r"(b0), "r"(b1));
}

__device__ __forceinline__ void cp16(uint32_t dst, const void* src) {
    asm volatile("cp.async.cg.shared.global [%0], [%1], 16;" :: "r"(dst), "l"(src) : "memory");
}

__device__ __forceinline__ void cp16_l2(uint32_t dst, const void* src) {
    asm volatile("cp.async.cg.shared.global.L2::256B [%0], [%1], 16;" :: "r"(dst), "l"(src) : "memory");
}

__device__ __forceinline__ float sqrt_approx(float x) {
    float r;
    asm("sqrt.approx.f32 %0, %1;" : "=f"(r) : "f"(x));
    return r;
}

// logical col l (within 16-group) -> physical smem row, so that mma fragment
// ownership {2t, 2t+1, 2t+8, 2t+9} (phys) maps to logical {4t..4t+3}.
__device__ __forceinline__ int bperm(int l) {
    int t = l >> 2, j = l & 3;
    return 2 * t + (j & 1) + ((j >> 1) << 3);
}

// ---------------- merged prep: fp32 -> bf16 (+E scaled by -2) + fp32 norms ----------------
__global__ __launch_bounds__(256)
void conv_all(const float* __restrict__ X, const float* __restrict__ E, int kblocks) {
    const int b    = blockIdx.x;
    const int tid  = threadIdx.x;
    const int lane = tid & 31;
    const float4* sv;
    __nv_bfloat16* drow;
    float* sqrow;
    float scale;
    if (b < kblocks) {
        sv    = reinterpret_cast<const float4*>(E) + (size_t)b * 2048;
        drow  = g_Ebf + (size_t)b * 8192;
        sqrow = g_esq + (size_t)b * 128;
        scale = -2.0f;
    } else {
        const int c = b - kblocks;
        sv    = reinterpret_cast<const float4*>(X) + (size_t)c * 2048;
        drow  = g_Xbf + (size_t)c * 8192;
        sqrow = g_xsq + (size_t)c * 128;
        scale = 1.0f;
    }
    #pragma unroll
    for (int i = 0; i < 8; i++) {
        const int f   = tid + i * 256;
        const int row = f >> 4;
        const int c4  = f & 15;
        float4 v = sv[f];
        float ss = v.x * v.x + v.y * v.y + v.z * v.z + v.w * v.w;  // norm of ORIGINAL
        __nv_bfloat162 p0 = __floats2bfloat162_rn(v.x * scale, v.y * scale);
        __nv_bfloat162 p1 = __floats2bfloat162_rn(v.z * scale, v.w * scale);
        uint2 pk;
        pk.x = *reinterpret_cast<uint32_t*>(&p0);
        pk.y = *reinterpret_cast<uint32_t*>(&p1);
        *reinterpret_cast<uint2*>(drow + row * 64 + c4 * 4) = pk;
        ss += __shfl_xor_sync(0xffffffffu, ss, 1);
        ss += __shfl_xor_sync(0xffffffffu, ss, 2);
        ss += __shfl_xor_sync(0xffffffffu, ss, 4);
        ss += __shfl_xor_sync(0xffffffffu, ss, 8);
        if ((lane & 15) == 0) sqrow[row] = ss;
    }
}

// ---------------- main ----------------
__device__ __forceinline__ void issue_A(uint32_t stg, int m0, int tid) {
    #pragma unroll
    for (int i = 0; i < 4; i++) {                  // 1024 chunks of 16B
        const int f   = tid + i * 256;
        const int row = f >> 3;
        const int c   = f & 7;
        cp16_l2(stg + SWZ((uint32_t)(row * 128 + c * 16)),
                g_Xbf + (size_t)(m0 + row) * 64 + c * 8);
    }
    if (tid < 32) cp16(stg + ST_XS + tid * 16, g_xsq + m0 + tid * 4);
}

__global__ __launch_bounds__(256, 2)
void vq_cdist_kernel(float* __restrict__ out, int Kdim, int nm, int nx) {
    extern __shared__ char smem[];
    const uint32_t s_base = (uint32_t)__cvta_generic_to_shared(smem);

    const int tid  = threadIdx.x;
    const int lane = tid & 31;
    const int wid  = tid >> 5;
    const int wm = (wid & 3) * 32;
    const int wn = (wid >> 2) * 32;

    const int group = blockIdx.x / nx;          // m-stripe group
    const int n0    = (blockIdx.x % nx) * BN;   // fixed n-tile for this CTA
    const int ng    = gridDim.x / nx;

    // ---- prologue: B tile + es (once), then first three A stages ----
    {
        const uint32_t b0 = s_base + B_OFF;
        #pragma unroll
        for (int i = 0; i < 2; i++) {              // 512 chunks (64 rows x 128B)
            const int f    = tid + i * 256;
            const int lrow = f >> 3;
            const int c    = f & 7;
            const int prow = (lrow & ~15) | bperm(lrow & 15);
            cp16(b0 + SWZ((uint32_t)(prow * 128 + c * 16)),
                 g_Ebf + (size_t)(n0 + lrow) * 64 + c * 8);
        }
        if (tid < 16) cp16(s_base + ES_OFF + tid * 16, g_esq + n0 + tid * 4);
        asm volatile("cp.async.commit_group;" ::: "memory");
    }
    // nm=512, ng>=16 -> every group has >= 26 tiles; prologue depth 3 is safe
    issue_A(s_base, group * BM, tid);
    asm volatile("cp.async.commit_group;" ::: "memory");
    issue_A(s_base + STAGE, (group + ng) * BM, tid);
    asm volatile("cp.async.commit_group;" ::: "memory");
    issue_A(s_base + 2 * STAGE, (group + 2 * ng) * BM, tid);
    asm volatile("cp.async.commit_group;" ::: "memory");

    asm volatile("cp.async.wait_group 3;" ::: "memory");       // B + es complete
    __syncthreads();

    // ---- persistent B fragments (32 regs) ----
    uint32_t bfr[4][2][4];
    #pragma unroll
    for (int ks = 0; ks < 4; ks++) {
        #pragma unroll
        for (int np = 0; np < 2; np++) {
            const int nr = wn + np * 16 + ((lane >> 4) & 1) * 8 + (lane & 7);
            const int kb = (ks * 16 + ((lane >> 3) & 1) * 8) * 2;
            ldsm_x4(bfr[ks][np][0], bfr[ks][np][1], bfr[ks][np][2], bfr[ks][np][3],
                    s_base + B_OFF + SWZ((uint32_t)(nr * 128 + kb)));
        }
    }
    // per-thread es values (8 floats), cached in registers
    const int rb = wm + (lane >> 2);
    const int t4 = (lane & 3) * 4;
    const float* es_s = reinterpret_cast<const float*>(smem + ES_OFF);
    const float4 esA = *reinterpret_cast<const float4*>(&es_s[wn + t4]);
    const float4 esB = *reinterpret_cast<const float4*>(&es_s[wn + 16 + t4]);

    // ---- main loop: 4 stages, distance-3 prefetch, 1 barrier/iter ----
    int st = 0;
    for (int mi = group; mi < nm; mi += ng) {
        __syncthreads();   // tile mi published; stage st-1 (=(st+3)&3) now dead

        const int mi3 = mi + 3 * ng;
        if (mi3 < nm) {
            issue_A(s_base + ((st + 3) & 3) * STAGE, mi3 * BM, tid);
            asm volatile("cp.async.commit_group;" ::: "memory");
            asm volatile("cp.async.wait_group 3;" ::: "memory");
        } else if (mi + 2 * ng < nm) {
            asm volatile("cp.async.wait_group 2;" ::: "memory");
        } else if (mi + ng < nm) {
            asm volatile("cp.async.wait_group 1;" ::: "memory");
        } else {
            asm volatile("cp.async.wait_group 0;" ::: "memory");
        }
        // wait_group guarantees tile mi's data has landed; the barrier above
        // ordered all warps past tile mi-1, so no warp can still read the
        // stage being overwritten.

        const uint32_t a_base = s_base + st * STAGE;
        const float* xs_s = reinterpret_cast<const float*>(smem + st * STAGE + ST_XS);
        const int m0 = mi * BM;

        // ---- acc init = xs + es (MMA adds -2*cross onto it) ----
        float acc[2][4][4];
        #pragma unroll
        for (int mt = 0; mt < 2; mt++) {
            const float xsa = xs_s[rb + mt * 16];
            const float xsb = xs_s[rb + mt * 16 + 8];
            acc[mt][0][0] = xsa + esA.x;  acc[mt][0][1] = xsa + esA.y;
            acc[mt][1][0] = xsa + esA.z;  acc[mt][1][1] = xsa + esA.w;
            acc[mt][0][2] = xsb + esA.x;  acc[mt][0][3] = xsb + esA.y;
            acc[mt][1][2] = xsb + esA.z;  acc[mt][1][3] = xsb + esA.w;
            acc[mt][2][0] = xsa + esB.x;  acc[mt][2][1] = xsa + esB.y;
            acc[mt][3][0] = xsa + esB.z;  acc[mt][3][1] = xsa + esB.w;
            acc[mt][2][2] = xsb + esB.x;  acc[mt][2][3] = xsb + esB.y;
            acc[mt][3][2] = xsb + esB.z;  acc[mt][3][3] = xsb + esB.w;
        }

        #pragma unroll
        for (int ks = 0; ks < 4; ks++) {
            const int kc = ks * 16;
            uint32_t a_frag[2][4];
            #pragma unroll
            for (int mt = 0; mt < 2; mt++) {
                const int r  = wm + mt * 16 + (lane & 15);
                const int cb = (kc + ((lane >> 4) << 3)) * 2;
                ldsm_x4(a_frag[mt][0], a_frag[mt][1], a_frag[mt][2], a_frag[mt][3],
                        a_base + SWZ((uint32_t)(r * 128 + cb)));
            }
            #pragma unroll
            for (int np = 0; np < 2; np++) {
                #pragma unroll
                for (int mt = 0; mt < 2; mt++) {
                    mma_bf16(acc[mt][np * 2],     a_frag[mt], bfr[ks][np][0], bfr[ks][np][1]);
                    mma_bf16(acc[mt][np * 2 + 1], a_frag[mt], bfr[ks][np][2], bfr[ks][np][3]);
                }
            }
        }

        // ---- epilogue: acc IS dist^2; sqrt + store only ----
        #pragma unroll
        for (int mt = 0; mt < 2; mt++) {
            const int lr0 = rb + mt * 16;
            const int lr1 = lr0 + 8;
            float* o0 = out + (size_t)(m0 + lr0) * Kdim + n0 + wn;
            float* o1 = out + (size_t)(m0 + lr1) * Kdim + n0 + wn;
            #pragma unroll
            for (int q = 0; q < 2; q++) {
                const int c = q * 16 + t4;
                float4 v0, v1;
                v0.x = sqrt_approx(acc[mt][2*q][0]);
                v0.y = sqrt_approx(acc[mt][2*q][1]);
                v0.z = sqrt_approx(acc[mt][2*q+1][0]);
                v0.w = sqrt_approx(acc[mt][2*q+1][1]);
                v1.x = sqrt_approx(acc[mt][2*q][2]);
                v1.y = sqrt_approx(acc[mt][2*q][3]);
                v1.z = sqrt_approx(acc[mt][2*q+1][2]);
                v1.w = sqrt_approx(acc[mt][2*q+1][3]);
                __stcs(reinterpret_cast<float4*>(o0 + c), v0);
                __stcs(reinterpret_cast<float4*>(o1 + c), v1);
            }
        }

        st = (st + 1) & 3;
    }
}

extern "C" void kernel_launch(void* const* d_in, const int* in_sizes, int n_in,
                              void* d_out, int out_size) {
    const float* X = (const float*)d_in[0];   // inputs [N, 64]
    const float* E = (const float*)d_in[1];   // embeddings [K, 64]
    float* out = (float*)d_out;               // [N, K] fp32

    const int N = in_sizes[0] / 64;
    const int K = in_sizes[1] / 64;
    const int nx = K / BN;                    // 16
    const int nm = N / BM;                    // 512

    static int configured = 0;
    if (!configured) {
        cudaFuncSetAttribute(vq_cdist_kernel,
                             cudaFuncAttributeMaxDynamicSharedMemorySize, DYN_SMEM);
        configured = 1;
    }

    int sms = 148;
    cudaDeviceGetAttribute(&sms, cudaDevAttrMultiProcessorCount, 0);
    int grid = (2 * sms / nx) * nx;           // multiple of nx
    if (grid < nx) grid = nx;

    conv_all<<<K / 128 + N / 128, 256>>>(X, E, K / 128);
    vq_cdist_kernel<<<grid, 256, DYN_SMEM>>>(out, K, nm, nx);
}